// round 1
// baseline (speedup 1.0000x reference)
#include <cuda_runtime.h>
#include <cstdint>

// Problem constants
#define B_    16
#define CIN_  512
#define COUT_ 512
#define H_    64
#define W_    64
#define SDIM_ 512

static __device__ __constant__ float MOD_SCALE_C  = 0.04419417382415922f;   // 1/sqrt(512)
static __device__ __constant__ float CONV_SCALE_C = 0.014731391274719742f;  // 1/sqrt(512*9)

// Scratch (device globals -- no allocation allowed)
__device__ float g_s[B_ * CIN_];        // modulation s[b,i]
__device__ float g_demod[B_ * COUT_];   // demod[b,o]
__device__ float g_wsqT[CIN_ * COUT_];  // wsq transposed: [i][o] = sum_k weight[o,i,k]^2

// ---------------------------------------------------------------------------
// Kernel 1: s[b,i] = sum_j style[b,j] * mod_weight[i,j] * MOD_SCALE + bias[i]
// grid = B_, block = 512 (one thread per input channel i)
// ---------------------------------------------------------------------------
__global__ void mod_kernel(const float* __restrict__ style,
                           const float* __restrict__ mod_weight,
                           const float* __restrict__ mod_bias) {
    __shared__ float st[SDIM_];
    int b = blockIdx.x;
    int i = threadIdx.x;
    st[i] = style[b * SDIM_ + i];
    __syncthreads();
    const float* wr = mod_weight + (size_t)i * SDIM_;
    float acc = 0.f;
#pragma unroll 8
    for (int j = 0; j < SDIM_; j++) acc = fmaf(st[j], wr[j], acc);
    g_s[b * CIN_ + i] = acc * MOD_SCALE_C + mod_bias[i];
}

// ---------------------------------------------------------------------------
// Kernel 2: wsqT[i][o] = sum_k weight[o,i,k]^2
// ---------------------------------------------------------------------------
__global__ void wsq_kernel(const float* __restrict__ weight) {
    int idx = blockIdx.x * blockDim.x + threadIdx.x;  // idx = i*COUT + o
    int i = idx / COUT_;
    int o = idx % COUT_;
    const float* w = weight + ((size_t)o * CIN_ + i) * 9;
    float acc = 0.f;
#pragma unroll
    for (int t = 0; t < 9; t++) acc = fmaf(w[t], w[t], acc);
    g_wsqT[i * COUT_ + o] = acc;
}

// ---------------------------------------------------------------------------
// Kernel 3: demod[b,o] = rsqrt(CONV_SCALE^2 * sum_i s[b,i]^2 * wsqT[i][o] + eps)
// grid = B_, block = 512 (one thread per output channel o)
// ---------------------------------------------------------------------------
__global__ void demod_kernel() {
    int b = blockIdx.x;
    int o = threadIdx.x;
    __shared__ float s2[CIN_];
    float sv = g_s[b * CIN_ + o];   // threadIdx doubles as i for the staging load
    s2[o] = sv * sv;
    __syncthreads();
    float acc = 0.f;
#pragma unroll 8
    for (int i = 0; i < CIN_; i++) acc = fmaf(s2[i], g_wsqT[i * COUT_ + o], acc);
    float cs2 = CONV_SCALE_C * CONV_SCALE_C;
    g_demod[b * COUT_ + o] = rsqrtf(acc * cs2 + 1e-8f);
}

// ---------------------------------------------------------------------------
// Kernel 4: main conv.
// out[b,o,y,x] = demod[b,o] * sum_{i,dy,dx} (weight[o,i,dy,dx]*s[b,i]*CONV_SCALE)
//                                           * x[b,i,y+dy-1,x+dx-1]
// CTA = (b, 64 out-channels, 32x4 spatial tile), 256 threads (8 warps).
// Warp ty owns 8 out-channels; thread tx owns column x0+tx across 4 rows.
// CIN processed in chunks of 8 staged through shared memory.
// ---------------------------------------------------------------------------
#define OT   64
#define TW   32
#define THh  4
#define CIT  8
#define WSTR 72   // padded (ci,tap) stride in sW: 16B-aligned, broadcast-friendly

__global__ void __launch_bounds__(256) conv_kernel(const float* __restrict__ x,
                                                   const float* __restrict__ weight,
                                                   float* __restrict__ out) {
    __shared__ __align__(16) float sIn[CIT][THh + 2][TW + 2];  // [8][6][34]
    __shared__ __align__(16) float sW[CIT * 9 * WSTR];         // [ci*9+tap][o(64) pad 72]

    const int b    = blockIdx.z;
    const int ob   = blockIdx.y;           // out-channel block (0..7)
    const int tile = blockIdx.x;           // 0..31
    const int x0   = (tile & 1) * TW;
    const int y0   = (tile >> 1) * THh;
    const int tid  = threadIdx.x;
    const int tx   = tid & 31;
    const int ty   = tid >> 5;             // warp id -> o-group

    float acc[8][THh];
#pragma unroll
    for (int oo = 0; oo < 8; oo++)
#pragma unroll
        for (int r = 0; r < THh; r++) acc[oo][r] = 0.f;

    const float* sb = g_s + b * CIN_;

    for (int ci0 = 0; ci0 < CIN_; ci0 += CIT) {
        __syncthreads();
        // stage input patch (zero-padded halo)
        for (int idx = tid; idx < CIT * 6 * 34; idx += 256) {
            int ci  = idx / (6 * 34);
            int rem = idx % (6 * 34);
            int r = rem / 34, c = rem % 34;
            int gy = y0 - 1 + r, gx = x0 - 1 + c;
            float v = 0.f;
            if ((unsigned)gy < H_ && (unsigned)gx < W_)
                v = x[(((size_t)b * CIN_ + ci0 + ci) * H_ + gy) * W_ + gx];
            sIn[ci][r][c] = v;
        }
        // stage weights, pre-scaled by s[b,ci]*CONV_SCALE (coalesced 288B reads)
        const float* wbase = weight + ((size_t)(ob * OT) * CIN_ + ci0) * 9;
        for (int idx = tid; idx < OT * 72; idx += 256) {
            int o = idx / 72, r = idx % 72;       // r = ci*9 + tap, ci in [0,8)
            int ci = r / 9;
            float sv = sb[ci0 + ci] * CONV_SCALE_C;
            float wv = wbase[(size_t)o * (CIN_ * 9) + r];
            sW[r * WSTR + o] = wv * sv;
        }
        __syncthreads();

#pragma unroll 2
        for (int ci = 0; ci < CIT; ci++) {
            float in[6][3];
#pragma unroll
            for (int r = 0; r < 6; r++)
#pragma unroll
                for (int c = 0; c < 3; c++) in[r][c] = sIn[ci][r][tx + c];

#pragma unroll
            for (int dy = 0; dy < 3; dy++) {
#pragma unroll
                for (int dx = 0; dx < 3; dx++) {
                    const int tap = dy * 3 + dx;
                    const float4* wp =
                        (const float4*)&sW[(ci * 9 + tap) * WSTR + ty * 8];
                    float4 w0 = wp[0], w1 = wp[1];
                    float wv[8] = {w0.x, w0.y, w0.z, w0.w, w1.x, w1.y, w1.z, w1.w};
#pragma unroll
                    for (int oo = 0; oo < 8; oo++)
#pragma unroll
                        for (int r = 0; r < THh; r++)
                            acc[oo][r] = fmaf(wv[oo], in[r + dy][dx], acc[oo][r]);
                }
            }
        }
    }

    // epilogue: demodulate and store (coalesced per (o,row))
#pragma unroll
    for (int oo = 0; oo < 8; oo++) {
        int o = ob * OT + ty * 8 + oo;
        float dm = g_demod[b * COUT_ + o];
#pragma unroll
        for (int r = 0; r < THh; r++) {
            out[(((size_t)b * COUT_ + o) * H_ + (y0 + r)) * W_ + x0 + tx] =
                acc[oo][r] * dm;
        }
    }
}

// ---------------------------------------------------------------------------
extern "C" void kernel_launch(void* const* d_in, const int* in_sizes, int n_in,
                              void* d_out, int out_size) {
    const float* x          = (const float*)d_in[0];
    const float* style      = (const float*)d_in[1];
    const float* weight     = (const float*)d_in[2];
    const float* mod_weight = (const float*)d_in[3];
    const float* mod_bias   = (const float*)d_in[4];
    float* out = (float*)d_out;

    mod_kernel<<<B_, SDIM_>>>(style, mod_weight, mod_bias);
    wsq_kernel<<<(CIN_ * COUT_) / 256, 256>>>(weight);
    demod_kernel<<<B_, COUT_>>>();

    dim3 grid(32, 8, B_);   // (spatial tiles, o-blocks, batch) = 4096 CTAs
    conv_kernel<<<grid, 256>>>(x, weight, out);
}

// round 3
// speedup vs baseline: 4.5833x; 4.5833x over previous
#include <cuda_runtime.h>
#include <cstdint>

// ======================= problem constants =======================
#define B_    16
#define CIN_  512
#define COUT_ 512
#define H_    64
#define W_    64
#define HW_   4096
#define SDIM_ 512

static __device__ __constant__ float MOD_SCALE_C  = 0.04419417382415922f;   // 1/sqrt(512)
static __device__ __constant__ float CONV_SCALE_C = 0.014731391274719742f;  // 1/sqrt(512*9)

// ======================= device scratch (no allocs allowed) =======================
__device__ float g_s[B_ * CIN_];
__device__ float g_demod[B_ * COUT_];
__device__ float g_wsqT[CIN_ * COUT_];
// tf32-rounded scaled input: [b*512+ci][y][x]
__device__ __align__(16) uint32_t g_xs[B_ * CIN_ * HW_];
// tf32-rounded weight taps: [tap][o][ci]
__device__ __align__(16) uint32_t g_wtap[9 * COUT_ * CIN_];

// ======================= helpers =======================
__device__ __forceinline__ uint32_t smem_to_u32(const void* p) {
    uint32_t a;
    asm("{ .reg .u64 t; cvta.to.shared.u64 t, %1; cvt.u32.u64 %0, t; }" : "=r"(a) : "l"(p));
    return a;
}
__device__ __forceinline__ uint32_t f2tf32(float f) {
    uint32_t r;
    asm("cvt.rn.tf32.f32 %0, %1;" : "=r"(r) : "f"(f));
    return r;
}

#define CP16(dst_s, src_g) \
    asm volatile("cp.async.cg.shared.global [%0], [%1], 16;" \
                 :: "r"(dst_s), "l"(src_g) : "memory")
#define CP_COMMIT() asm volatile("cp.async.commit_group;" ::: "memory")
#define CP_WAIT0()  asm volatile("cp.async.wait_group 0;" ::: "memory")

#define MMA_TF32(d, a0, a1, a2, a3, b0, b1)                                  \
    asm volatile("mma.sync.aligned.m16n8k8.row.col.f32.tf32.tf32.f32 "       \
        "{%0,%1,%2,%3}, {%4,%5,%6,%7}, {%8,%9}, {%0,%1,%2,%3};"              \
        : "+f"((d)[0]), "+f"((d)[1]), "+f"((d)[2]), "+f"((d)[3])             \
        : "r"(a0), "r"(a1), "r"(a2), "r"(a3), "r"(b0), "r"(b1))

// ======================= prep kernels =======================
__global__ void mod_kernel(const float* __restrict__ style,
                           const float* __restrict__ mod_weight,
                           const float* __restrict__ mod_bias) {
    __shared__ float st[SDIM_];
    int b = blockIdx.x, i = threadIdx.x;
    st[i] = style[b * SDIM_ + i];
    __syncthreads();
    const float* wr = mod_weight + (size_t)i * SDIM_;
    float acc = 0.f;
#pragma unroll 8
    for (int j = 0; j < SDIM_; j++) acc = fmaf(st[j], wr[j], acc);
    g_s[b * CIN_ + i] = acc * MOD_SCALE_C + mod_bias[i];
}

__global__ void wsq_kernel(const float* __restrict__ weight) {
    int idx = blockIdx.x * blockDim.x + threadIdx.x;
    int i = idx / COUT_, o = idx % COUT_;
    const float* w = weight + ((size_t)o * CIN_ + i) * 9;
    float acc = 0.f;
#pragma unroll
    for (int t = 0; t < 9; t++) acc = fmaf(w[t], w[t], acc);
    g_wsqT[i * COUT_ + o] = acc;
}

__global__ void demod_kernel() {
    int b = blockIdx.x, o = threadIdx.x;
    __shared__ float s2[CIN_];
    float sv = g_s[b * CIN_ + o];
    s2[o] = sv * sv;
    __syncthreads();
    float acc = 0.f;
#pragma unroll 8
    for (int i = 0; i < CIN_; i++) acc = fmaf(s2[i], g_wsqT[i * COUT_ + o], acc);
    float cs2 = CONV_SCALE_C * CONV_SCALE_C;
    g_demod[b * COUT_ + o] = rsqrtf(acc * cs2 + 1e-8f);
}

// transpose weight into per-tap matrices [tap][o][ci], tf32-rounded
__global__ void wtap_kernel(const float* __restrict__ weight) {
    int idx = blockIdx.x * blockDim.x + threadIdx.x;   // o*512 + ci
    int o = idx / CIN_, ci = idx % CIN_;
    const float* w = weight + (size_t)idx * 9;
#pragma unroll
    for (int t = 0; t < 9; t++)
        g_wtap[((size_t)t * COUT_ + o) * CIN_ + ci] = f2tf32(w[t]);
}

// x_scaled[b,ci,pix] = tf32_rn(x * s[b,ci] * CONV_SCALE)
__global__ void xs_kernel(const float* __restrict__ x) {
    int idx = blockIdx.x * blockDim.x + threadIdx.x;   // float4 index
    int bci = idx >> 10;
    float sc = g_s[bci] * CONV_SCALE_C;
    float4 v = ((const float4*)x)[idx];
    uint4 r;
    r.x = f2tf32(v.x * sc);
    r.y = f2tf32(v.y * sc);
    r.z = f2tf32(v.z * sc);
    r.w = f2tf32(v.w * sc);
    ((uint4*)g_xs)[idx] = r;
}

// ======================= main mma.sync conv kernel =======================
// CTA tile: M=128 outch x N=128 px (2 rows of 64). 8 warps (2m x 4n), warp 64x32.
// K = 9 taps x 512 ci; 144 stages of 32. B halo tile reused across the 9 taps
// of a ci-chunk; taps are smem pointer shifts (halo cols pre-zeroed).
//
// smem (words): A0[0,4608) A1[4608,9216) B0[9216,+9472) B1[+9472)
//   A stage: 128 rows x stride 36 (32 data + pad)   = 4608 w (18432 B)
//   B stage: 32 ci x stride 296 ( 4 rows x 72 cols) = 9472 w (37888 B)
#define ASTAGE_W 4608
#define BSTAGE_W 9472
#define B0_W     9216
#define SMEM_W   (2 * ASTAGE_W + 2 * BSTAGE_W)   // 28160 words = 112640 B

__global__ void __launch_bounds__(256, 2)
conv_mma_kernel(float* __restrict__ out) {
    extern __shared__ uint32_t smem[];
    const uint32_t smem_u = smem_to_u32(smem);

    const int tid  = threadIdx.x;
    const int wid  = tid >> 5, lane = tid & 31;
    const int gid  = lane >> 2, tig = lane & 3;
    const int wm   = wid >> 2, wn = wid & 3;      // 2 m-warps x 4 n-warps
    const int nt   = blockIdx.x, mt = blockIdx.y, b = blockIdx.z;
    const int y0   = nt * 2;                      // 2 output rows per CTA
    const int m0   = mt * 128;

    // zero both B buffers once: halo cols (x=-4..-1, 64..67) and y-OOB rows
    // stay zero forever; valid region is overwritten every chunk.
#pragma unroll 4
    for (int i = tid; i < (2 * BSTAGE_W) / 4; i += 256)
        ((uint4*)(smem + B0_W))[i] = make_uint4(0, 0, 0, 0);
    __syncthreads();

    // -------- cp.async issuers --------
    auto issueA = [&](int s) {   // stage s: tap = s%9, chunk = s/9
        const int tap = s % 9, ci0 = (s / 9) * 32;
        const uint32_t dst = smem_u + ((s & 1) * ASTAGE_W) * 4;
        const uint32_t* src = g_wtap + ((size_t)tap * COUT_ + m0) * CIN_ + ci0;
#pragma unroll
        for (int i = 0; i < 4; i++) {
            int idx = tid + i * 256;             // 1024 x 16B chunks
            int row = idx >> 3, cg = idx & 7;
            CP16(dst + row * 144 + cg * 16, src + (size_t)row * CIN_ + cg * 4);
        }
    };
    auto issueB = [&](int c) {   // ci-chunk c
        const int ci0 = c * 32;
        const uint32_t dst = smem_u + (B0_W + (c & 1) * BSTAGE_W) * 4;
#pragma unroll
        for (int i = 0; i < 8; i++) {
            int idx = tid + i * 256;             // 2048 x 16B chunks
            int ci = idx >> 6, rem = idx & 63;
            int r = rem >> 4, cg = rem & 15;
            int y = y0 - 1 + r;
            if ((unsigned)y < H_)
                CP16(dst + ci * 1184 + r * 288 + 16 + cg * 16,
                     g_xs + (((size_t)(b * CIN_ + ci0 + ci)) * H_ + y) * W_ + cg * 4);
        }
    };

    float acc[4][4][4];
#pragma unroll
    for (int mf = 0; mf < 4; mf++)
#pragma unroll
        for (int nf = 0; nf < 4; nf++)
#pragma unroll
            for (int k = 0; k < 4; k++) acc[mf][nf][k] = 0.f;

    // prologue
    issueB(0);
    issueA(0);
    CP_COMMIT();

    const int rbase = wn >> 1;                   // output row within tile
    const int cbase = (wn & 1) * 32 + gid;       // output col base for B frags

    for (int s = 0; s < 144; s++) {
        CP_WAIT0();
        __syncthreads();
        if (s + 1 < 144) {
            issueA(s + 1);
            if ((s + 1) % 9 == 0) issueB((s + 1) / 9);
            CP_COMMIT();
        }

        const int tap = s % 9, chunk = s / 9;
        const int dy = tap / 3, dx = tap % 3;
        const uint32_t* Aw = smem + (s & 1) * ASTAGE_W + (wm * 64 + gid) * 36 + tig;
        const uint32_t* Bw = smem + B0_W + (chunk & 1) * BSTAGE_W
                             + tig * 296 + (rbase + dy) * 72 + cbase + dx + 3;
#pragma unroll
        for (int ks = 0; ks < 4; ks++) {
            uint32_t b0[4], b1[4];
#pragma unroll
            for (int nf = 0; nf < 4; nf++) {
                b0[nf] = Bw[ks * 2368 + nf * 8];
                b1[nf] = Bw[ks * 2368 + nf * 8 + 1184];
            }
#pragma unroll
            for (int mf = 0; mf < 4; mf++) {
                uint32_t a0 = Aw[mf * 576 + ks * 8];
                uint32_t a1 = Aw[mf * 576 + ks * 8 + 288];
                uint32_t a2 = Aw[mf * 576 + ks * 8 + 4];
                uint32_t a3 = Aw[mf * 576 + ks * 8 + 292];
#pragma unroll
                for (int nf = 0; nf < 4; nf++)
                    MMA_TF32(acc[mf][nf], a0, a1, a2, a3, b0[nf], b1[nf]);
            }
        }
    }

    // -------- epilogue: demodulate + store --------
    const int y = y0 + (wn >> 1);
#pragma unroll
    for (int mf = 0; mf < 4; mf++) {
        const int o0 = m0 + wm * 64 + mf * 16 + gid;
        const float dmlo = g_demod[b * COUT_ + o0];
        const float dmhi = g_demod[b * COUT_ + o0 + 8];
        float* plo = out + (((size_t)b * COUT_ + o0) * H_ + y) * W_;
        float* phi = plo + 8 * (size_t)HW_;
#pragma unroll
        for (int nf = 0; nf < 4; nf++) {
            const int x = (wn & 1) * 32 + nf * 8 + 2 * tig;
            float2 vlo, vhi;
            vlo.x = acc[mf][nf][0] * dmlo;
            vlo.y = acc[mf][nf][1] * dmlo;
            vhi.x = acc[mf][nf][2] * dmhi;
            vhi.y = acc[mf][nf][3] * dmhi;
            *(float2*)(plo + x) = vlo;
            *(float2*)(phi + x) = vhi;
        }
    }
}

// ======================= host side =======================
extern "C" void kernel_launch(void* const* d_in, const int* in_sizes, int n_in,
                              void* d_out, int out_size) {
    const float* x          = (const float*)d_in[0];
    const float* style      = (const float*)d_in[1];
    const float* weight     = (const float*)d_in[2];
    const float* mod_weight = (const float*)d_in[3];
    const float* mod_bias   = (const float*)d_in[4];
    float* out = (float*)d_out;

    mod_kernel<<<B_, SDIM_>>>(style, mod_weight, mod_bias);
    wsq_kernel<<<(CIN_ * COUT_) / 256, 256>>>(weight);
    demod_kernel<<<B_, COUT_>>>();
    wtap_kernel<<<(COUT_ * CIN_) / 256, 256>>>(weight);
    xs_kernel<<<(B_ * CIN_ * HW_ / 4) / 256, 256>>>(x);

    static bool configured = false;
    if (!configured) {
        cudaFuncSetAttribute(conv_mma_kernel,
                             cudaFuncAttributeMaxDynamicSharedMemorySize,
                             SMEM_W * 4);
        configured = true;
    }
    dim3 grid(32, 4, B_);   // (n-tiles, m-tiles, batch) = 2048 CTAs
    conv_mma_kernel<<<grid, 256, SMEM_W * 4>>>(out);
}

// round 5
// speedup vs baseline: 7.3450x; 1.6025x over previous
#include <cuda_runtime.h>
#include <cuda_fp16.h>
#include <cstdint>

// ======================= problem constants =======================
#define B_    16
#define CIN_  512
#define COUT_ 512
#define H_    64
#define W_    64
#define HW_   4096
#define SDIM_ 512

static __device__ __constant__ float MOD_SCALE_C  = 0.04419417382415922f;   // 1/sqrt(512)
static __device__ __constant__ float CONV_SCALE_C = 0.014731391274719742f;  // 1/sqrt(512*9)

// ======================= device scratch (no allocs allowed) =======================
__device__ float g_s[B_ * CIN_];
__device__ float g_demod[B_ * COUT_];
__device__ float g_wsqT[CIN_ * COUT_];
// f16 scaled input, channel-pair interleaved: word[b][c2][y][x] = {x[2c2], x[2c2+1]} * s * CONV_SCALE
__device__ __align__(16) uint32_t g_xs2[B_ * (CIN_ / 2) * HW_];
// f16 weight taps: [tap][o][ci]
__device__ __align__(16) __half g_wtap[9 * COUT_ * CIN_];

// ======================= helpers =======================
__device__ __forceinline__ uint32_t smem_to_u32(const void* p) {
    uint32_t a;
    asm("{ .reg .u64 t; cvta.to.shared.u64 t, %1; cvt.u32.u64 %0, t; }" : "=r"(a) : "l"(p));
    return a;
}
__device__ __forceinline__ uint32_t pack_half2(float lo, float hi) {
    // bit-pack two f16 values into one 32-bit word: lo in bits [0:16), hi in [16:32)
    uint32_t l = (uint32_t)__half_as_ushort(__float2half_rn(lo));
    uint32_t h = (uint32_t)__half_as_ushort(__float2half_rn(hi));
    return l | (h << 16);
}

#define CP16(dst_s, src_g) \
    asm volatile("cp.async.cg.shared.global [%0], [%1], 16;" \
                 :: "r"(dst_s), "l"(src_g) : "memory")
#define CP_COMMIT() asm volatile("cp.async.commit_group;" ::: "memory")
#define CP_WAIT0()  asm volatile("cp.async.wait_group 0;" ::: "memory")

// f16 mma, fp32 accumulate: D(16x8) += A(16x16) * B(16x8)
#define MMA_F16(d, a0, a1, a2, a3, b0, b1)                                   \
    asm volatile("mma.sync.aligned.m16n8k16.row.col.f32.f16.f16.f32 "        \
        "{%0,%1,%2,%3}, {%4,%5,%6,%7}, {%8,%9}, {%0,%1,%2,%3};"              \
        : "+f"((d)[0]), "+f"((d)[1]), "+f"((d)[2]), "+f"((d)[3])             \
        : "r"(a0), "r"(a1), "r"(a2), "r"(a3), "r"(b0), "r"(b1))

// ======================= prep kernels =======================
__global__ void mod_kernel(const float* __restrict__ style,
                           const float* __restrict__ mod_weight,
                           const float* __restrict__ mod_bias) {
    __shared__ float st[SDIM_];
    int b = blockIdx.x, i = threadIdx.x;
    st[i] = style[b * SDIM_ + i];
    __syncthreads();
    const float* wr = mod_weight + (size_t)i * SDIM_;
    float acc = 0.f;
#pragma unroll 8
    for (int j = 0; j < SDIM_; j++) acc = fmaf(st[j], wr[j], acc);
    g_s[b * CIN_ + i] = acc * MOD_SCALE_C + mod_bias[i];
}

__global__ void wsq_kernel(const float* __restrict__ weight) {
    int idx = blockIdx.x * blockDim.x + threadIdx.x;
    int i = idx / COUT_, o = idx % COUT_;
    const float* w = weight + ((size_t)o * CIN_ + i) * 9;
    float acc = 0.f;
#pragma unroll
    for (int t = 0; t < 9; t++) acc = fmaf(w[t], w[t], acc);
    g_wsqT[i * COUT_ + o] = acc;
}

__global__ void demod_kernel() {
    int b = blockIdx.x, o = threadIdx.x;
    __shared__ float s2[CIN_];
    float sv = g_s[b * CIN_ + o];
    s2[o] = sv * sv;
    __syncthreads();
    float acc = 0.f;
#pragma unroll 8
    for (int i = 0; i < CIN_; i++) acc = fmaf(s2[i], g_wsqT[i * COUT_ + o], acc);
    float cs2 = CONV_SCALE_C * CONV_SCALE_C;
    g_demod[b * COUT_ + o] = rsqrtf(acc * cs2 + 1e-8f);
}

// weight -> f16 per-tap matrices [tap][o][ci]
__global__ void wtap_kernel(const float* __restrict__ weight) {
    int idx = blockIdx.x * blockDim.x + threadIdx.x;   // o*512 + ci
    int o = idx / CIN_, ci = idx % CIN_;
    const float* w = weight + (size_t)idx * 9;
#pragma unroll
    for (int t = 0; t < 9; t++)
        g_wtap[((size_t)t * COUT_ + o) * CIN_ + ci] = __float2half_rn(w[t]);
}

// x -> f16 half2(channel-pair) images, scaled by s * CONV_SCALE
__global__ void xs2_kernel(const float* __restrict__ x) {
    int idx = blockIdx.x * blockDim.x + threadIdx.x;   // (b, c2, pix4)
    int bc2 = idx >> 10;                               // 1024 pix4 per image
    int p4  = (idx & 1023) * 4;
    int b = bc2 >> 8, c2 = bc2 & 255;
    float sc0 = g_s[b * CIN_ + 2 * c2]     * CONV_SCALE_C;
    float sc1 = g_s[b * CIN_ + 2 * c2 + 1] * CONV_SCALE_C;
    const float4 v0 = *(const float4*)(x + ((size_t)(b * CIN_ + 2 * c2))     * HW_ + p4);
    const float4 v1 = *(const float4*)(x + ((size_t)(b * CIN_ + 2 * c2 + 1)) * HW_ + p4);
    uint4 r;
    r.x = pack_half2(v0.x * sc0, v1.x * sc1);
    r.y = pack_half2(v0.y * sc0, v1.y * sc1);
    r.z = pack_half2(v0.z * sc0, v1.z * sc1);
    r.w = pack_half2(v0.w * sc0, v1.w * sc1);
    ((uint4*)g_xs2)[idx] = r;
}

// ======================= main mma.sync f16 conv kernel =======================
// CTA tile: M=128 outch x N=128 px (2 rows of 64). 8 warps (2m x 4n), warp 64x32.
// K = 9 taps x 512 ci; 144 stages of 32 ci (= 2 k16-steps). Halo B tile (half2
// channel pairs, col innermost) reused across the 9 taps of each ci-chunk.
//
// smem (32-bit words):
//   A stage: 128 rows x stride 20 (16 data words = 32 f16 + 4 pad) = 2560 w
//   B stage: 16 c2 x stride 296 (4 rows x 72 cols + 8 pad)         = 4736 w
#define ASTAGE_W 2560
#define BSTAGE_W 4736
#define B0_W     (2 * ASTAGE_W)                  // 5120
#define SMEM_W   (2 * ASTAGE_W + 2 * BSTAGE_W)   // 14592 words = 58368 B

__global__ void __launch_bounds__(256, 2)
conv_mma_kernel(float* __restrict__ out) {
    extern __shared__ uint32_t smem[];
    const uint32_t smem_u = smem_to_u32(smem);

    const int tid  = threadIdx.x;
    const int wid  = tid >> 5, lane = tid & 31;
    const int gid  = lane >> 2, tig = lane & 3;
    const int wm   = wid >> 2, wn = wid & 3;      // 2 m-warps x 4 n-warps
    const int nt   = blockIdx.x, mt = blockIdx.y, b = blockIdx.z;
    const int y0   = nt * 2;                      // 2 output rows per CTA
    const int m0   = mt * 128;

    // zero both B buffers once: halo cols + y-OOB rows stay zero forever.
    for (int i = tid; i < (2 * BSTAGE_W) / 4; i += 256)
        ((uint4*)(smem + B0_W))[i] = make_uint4(0, 0, 0, 0);
    __syncthreads();

    // -------- cp.async issuers --------
    auto issueA = [&](int s) {   // stage s: tap = s%9, chunk = s/9
        const int tap = s % 9, ci0 = (s / 9) * 32;
        const uint32_t dst = smem_u + ((s & 1) * ASTAGE_W) * 4;
        const __half* src = g_wtap + ((size_t)tap * COUT_ + m0) * CIN_ + ci0;
#pragma unroll
        for (int i = 0; i < 2; i++) {
            int idx = tid + i * 256;             // 512 x 16B chunks
            int row = idx >> 2, cg = idx & 3;    // 4 chunks per 128-row
            CP16(dst + row * 80 + cg * 16, src + (size_t)row * CIN_ + cg * 8);
        }
    };
    auto issueB = [&](int c) {   // ci-chunk c (32 ci = 16 half2 channels)
        const int c20 = c * 16;
        const uint32_t dst = smem_u + (B0_W + (c & 1) * BSTAGE_W) * 4;
#pragma unroll
        for (int i = 0; i < 4; i++) {
            int idx = tid + i * 256;             // 1024 x 16B chunks
            int c2 = idx >> 6, rem = idx & 63;   // 64 chunks per c2
            int r = rem >> 4, cg = rem & 15;     // 4 rows x 16 col-chunks
            int y = y0 - 1 + r;
            if ((unsigned)y < H_)
                CP16(dst + c2 * 1184 + r * 288 + 16 + cg * 16,
                     g_xs2 + (((size_t)(b * (CIN_ / 2) + c20 + c2)) * H_ + y) * W_ + cg * 4);
        }
    };

    float acc[4][4][4];
#pragma unroll
    for (int mf = 0; mf < 4; mf++)
#pragma unroll
        for (int nf = 0; nf < 4; nf++)
#pragma unroll
            for (int k = 0; k < 4; k++) acc[mf][nf][k] = 0.f;

    // prologue
    issueB(0);
    issueA(0);
    CP_COMMIT();

    const int rbase = wn >> 1;                   // output row within tile (0/1)
    const int cbase = (wn & 1) * 32 + gid;       // output col base for B frags

    for (int s = 0; s < 144; s++) {
        CP_WAIT0();
        __syncthreads();
        if (s + 1 < 144) {
            issueA(s + 1);
            if ((s + 1) % 9 == 0) issueB((s + 1) / 9);
            CP_COMMIT();
        }

        const int tap = s % 9, chunk = s / 9;
        const int dy = tap / 3, dx = tap % 3;
        // A: row stride 20 words; frag word tig holds halves (2tig, 2tig+1)
        const uint32_t* Aw = smem + (s & 1) * ASTAGE_W + (wm * 64 + gid) * 20 + tig;
        // B: c2 stride 296 words; word = half2{ci even, ci odd} at one pixel
        const uint32_t* Bw = smem + B0_W + (chunk & 1) * BSTAGE_W
                             + tig * 296 + (rbase + dy) * 72 + cbase + dx + 3;
#pragma unroll
        for (int ks = 0; ks < 2; ks++) {         // 2 x k16 per 32-ci chunk
            uint32_t b0[4], b1[4];
#pragma unroll
            for (int nf = 0; nf < 4; nf++) {
                b0[nf] = Bw[ks * 2368 + nf * 8];           // c2 = tig   (+8ks)
                b1[nf] = Bw[ks * 2368 + nf * 8 + 1184];    // c2 = tig+4 (+8ks)
            }
#pragma unroll
            for (int mf = 0; mf < 4; mf++) {
                uint32_t a0 = Aw[mf * 320 + ks * 8];        // row gid,   k lo
                uint32_t a1 = Aw[mf * 320 + ks * 8 + 160];  // row gid+8, k lo
                uint32_t a2 = Aw[mf * 320 + ks * 8 + 4];    // row gid,   k hi
                uint32_t a3 = Aw[mf * 320 + ks * 8 + 164];  // row gid+8, k hi
#pragma unroll
                for (int nf = 0; nf < 4; nf++)
                    MMA_F16(acc[mf][nf], a0, a1, a2, a3, b0[nf], b1[nf]);
            }
        }
    }

    // -------- epilogue: demodulate + store --------
    const int y = y0 + (wn >> 1);
#pragma unroll
    for (int mf = 0; mf < 4; mf++) {
        const int o0 = m0 + wm * 64 + mf * 16 + gid;
        const float dmlo = g_demod[b * COUT_ + o0];
        const float dmhi = g_demod[b * COUT_ + o0 + 8];
        float* plo = out + (((size_t)b * COUT_ + o0) * H_ + y) * W_;
        float* phi = plo + 8 * (size_t)HW_;
#pragma unroll
        for (int nf = 0; nf < 4; nf++) {
            const int x = (wn & 1) * 32 + nf * 8 + 2 * tig;
            float2 vlo, vhi;
            vlo.x = acc[mf][nf][0] * dmlo;
            vlo.y = acc[mf][nf][1] * dmlo;
            vhi.x = acc[mf][nf][2] * dmhi;
            vhi.y = acc[mf][nf][3] * dmhi;
            *(float2*)(plo + x) = vlo;
            *(float2*)(phi + x) = vhi;
        }
    }
}

// ======================= host side =======================
extern "C" void kernel_launch(void* const* d_in, const int* in_sizes, int n_in,
                              void* d_out, int out_size) {
    const float* x          = (const float*)d_in[0];
    const float* style      = (const float*)d_in[1];
    const float* weight     = (const float*)d_in[2];
    const float* mod_weight = (const float*)d_in[3];
    const float* mod_bias   = (const float*)d_in[4];
    float* out = (float*)d_out;

    mod_kernel<<<B_, SDIM_>>>(style, mod_weight, mod_bias);
    wsq_kernel<<<(CIN_ * COUT_) / 256, 256>>>(weight);
    demod_kernel<<<B_, COUT_>>>();
    wtap_kernel<<<(COUT_ * CIN_) / 256, 256>>>(weight);
    xs2_kernel<<<(B_ * (CIN_ / 2) * HW_ / 4) / 256, 256>>>(x);

    static bool configured = false;
    if (!configured) {
        cudaFuncSetAttribute(conv_mma_kernel,
                             cudaFuncAttributeMaxDynamicSharedMemorySize,
                             SMEM_W * 4);
        configured = true;
    }
    dim3 grid(32, 4, B_);   // (n-tiles, m-tiles, batch) = 2048 CTAs
    conv_mma_kernel<<<grid, 256, SMEM_W * 4>>>(out);
}

// round 6
// speedup vs baseline: 7.9059x; 1.0764x over previous
#include <cuda_runtime.h>
#include <cuda_fp16.h>
#include <cstdint>

// ======================= problem constants =======================
#define B_    16
#define CIN_  512
#define COUT_ 512
#define H_    64
#define W_    64
#define HW_   4096
#define SDIM_ 512

static __device__ __constant__ float MOD_SCALE_C  = 0.04419417382415922f;   // 1/sqrt(512)
static __device__ __constant__ float CONV_SCALE_C = 0.014731391274719742f;  // 1/sqrt(512*9)

// ======================= device scratch (no allocs allowed) =======================
__device__ float g_s[B_ * CIN_];
__device__ float g_demod[B_ * COUT_];
__device__ float g_wsqT[CIN_ * COUT_];
// f16 scaled input, channel-pair interleaved: word[b][c2][y][x] = {x[2c2], x[2c2+1]} * s * CONV_SCALE
__device__ __align__(16) uint32_t g_xs2[B_ * (CIN_ / 2) * HW_];
// f16 weight taps: [tap][o][ci]
__device__ __align__(16) __half g_wtap[9 * COUT_ * CIN_];

// ======================= helpers =======================
__device__ __forceinline__ uint32_t smem_to_u32(const void* p) {
    uint32_t a;
    asm("{ .reg .u64 t; cvta.to.shared.u64 t, %1; cvt.u32.u64 %0, t; }" : "=r"(a) : "l"(p));
    return a;
}
__device__ __forceinline__ uint32_t pack_half2(float lo, float hi) {
    uint32_t l = (uint32_t)__half_as_ushort(__float2half_rn(lo));
    uint32_t h = (uint32_t)__half_as_ushort(__float2half_rn(hi));
    return l | (h << 16);
}

#define CP16(dst_s, src_g) \
    asm volatile("cp.async.cg.shared.global [%0], [%1], 16;" \
                 :: "r"(dst_s), "l"(src_g) : "memory")
#define CP_COMMIT() asm volatile("cp.async.commit_group;" ::: "memory")
#define CP_WAIT0()  asm volatile("cp.async.wait_group 0;" ::: "memory")

// f16 mma, fp32 accumulate: D(16x8) += A(16x16) * B(16x8)
#define MMA_F16(d, a0, a1, a2, a3, b0, b1)                                   \
    asm volatile("mma.sync.aligned.m16n8k16.row.col.f32.f16.f16.f32 "        \
        "{%0,%1,%2,%3}, {%4,%5,%6,%7}, {%8,%9}, {%0,%1,%2,%3};"              \
        : "+f"((d)[0]), "+f"((d)[1]), "+f"((d)[2]), "+f"((d)[3])             \
        : "r"(a0), "r"(a1), "r"(a2), "r"(a3), "r"(b0), "r"(b1))

// ======================= prep kernel 1 (fused mod + wsq + wtap) =======================
// blocks [0,16): modulation; [16,528): wsq; [528,1040): wtap.  512 threads.
__global__ void __launch_bounds__(512) prep1_kernel(const float* __restrict__ style,
                                                    const float* __restrict__ mod_weight,
                                                    const float* __restrict__ mod_bias,
                                                    const float* __restrict__ weight) {
    const int blk = blockIdx.x, tid = threadIdx.x;
    if (blk < 16) {
        __shared__ float st[SDIM_];
        int b = blk, i = tid;
        st[i] = style[b * SDIM_ + i];
        __syncthreads();
        const float* wr = mod_weight + (size_t)i * SDIM_;
        float acc = 0.f;
#pragma unroll 8
        for (int j = 0; j < SDIM_; j++) acc = fmaf(st[j], wr[j], acc);
        g_s[b * CIN_ + i] = acc * MOD_SCALE_C + mod_bias[i];
    } else if (blk < 528) {
        int idx = (blk - 16) * 512 + tid;       // i*COUT + o
        int i = idx / COUT_, o = idx % COUT_;
        const float* w = weight + ((size_t)o * CIN_ + i) * 9;
        float acc = 0.f;
#pragma unroll
        for (int t = 0; t < 9; t++) acc = fmaf(w[t], w[t], acc);
        g_wsqT[i * COUT_ + o] = acc;
    } else {
        int idx = (blk - 528) * 512 + tid;      // o*512 + ci
        int o = idx / CIN_, ci = idx % CIN_;
        const float* w = weight + (size_t)idx * 9;
#pragma unroll
        for (int t = 0; t < 9; t++)
            g_wtap[((size_t)t * COUT_ + o) * CIN_ + ci] = __float2half_rn(w[t]);
    }
}

__global__ void demod_kernel() {
    int b = blockIdx.x, o = threadIdx.x;
    __shared__ float s2[CIN_];
    float sv = g_s[b * CIN_ + o];
    s2[o] = sv * sv;
    __syncthreads();
    float acc = 0.f;
#pragma unroll 8
    for (int i = 0; i < CIN_; i++) acc = fmaf(s2[i], g_wsqT[i * COUT_ + o], acc);
    float cs2 = CONV_SCALE_C * CONV_SCALE_C;
    g_demod[b * COUT_ + o] = rsqrtf(acc * cs2 + 1e-8f);
}

// x -> f16 half2(channel-pair) images, scaled by s * CONV_SCALE
__global__ void __launch_bounds__(512) xs2_kernel(const float* __restrict__ x) {
    int idx = blockIdx.x * 512 + threadIdx.x;          // (b, c2, pix4)
    int bc2 = idx >> 10;                               // 1024 pix4 per image
    int p4  = (idx & 1023) * 4;
    int b = bc2 >> 8, c2 = bc2 & 255;
    float sc0 = g_s[b * CIN_ + 2 * c2]     * CONV_SCALE_C;
    float sc1 = g_s[b * CIN_ + 2 * c2 + 1] * CONV_SCALE_C;
    const float4 v0 = *(const float4*)(x + ((size_t)(b * CIN_ + 2 * c2))     * HW_ + p4);
    const float4 v1 = *(const float4*)(x + ((size_t)(b * CIN_ + 2 * c2 + 1)) * HW_ + p4);
    uint4 r;
    r.x = pack_half2(v0.x * sc0, v1.x * sc1);
    r.y = pack_half2(v0.y * sc0, v1.y * sc1);
    r.z = pack_half2(v0.z * sc0, v1.z * sc1);
    r.w = pack_half2(v0.w * sc0, v1.w * sc1);
    ((uint4*)g_xs2)[idx] = r;
}

// ======================= main mma.sync f16 conv kernel =======================
// CTA tile: M=128 outch x N=256 px (4 rows of 64). 8 warps (2m x 4n);
// warp tile 64x64: n-warp wn owns output row y0+wn, 4mf x 8nf x 2ks = 64 mma/stage.
// K = 9 taps x 512 ci; 144 stages of 32 ci. B halo tile (16 c2 x 6 rows x 72 cols)
// reused across the 9 taps of each ci-chunk; taps = smem pointer shifts.
//
// smem (32-bit words):
//   A stage: 128 rows x stride 20 (16 data words = 32 f16 + 4 pad) = 2560 w
//   B stage: 16 c2 x stride 440 (6 rows x 72 cols + 8 pad)         = 7040 w
#define ASTAGE_W 2560
#define BSTAGE_W 7040
#define B0_W     (2 * ASTAGE_W)                  // 5120
#define SMEM_W   (2 * ASTAGE_W + 2 * BSTAGE_W)   // 19200 words = 76800 B

__global__ void __launch_bounds__(256, 1)
conv_mma_kernel(float* __restrict__ out) {
    extern __shared__ uint32_t smem[];
    const uint32_t smem_u = smem_to_u32(smem);

    const int tid  = threadIdx.x;
    const int wid  = tid >> 5, lane = tid & 31;
    const int gid  = lane >> 2, tig = lane & 3;
    const int wm   = wid >> 2, wn = wid & 3;      // 2 m-warps x 4 n-warps
    const int nt   = blockIdx.x, mt = blockIdx.y, b = blockIdx.z;
    const int y0   = nt * 4;                      // 4 output rows per CTA
    const int m0   = mt * 128;

    // zero both B buffers once: halo cols + y-OOB rows stay zero forever.
    for (int i = tid; i < (2 * BSTAGE_W) / 4; i += 256)
        ((uint4*)(smem + B0_W))[i] = make_uint4(0, 0, 0, 0);
    __syncthreads();

    // -------- cp.async issuers --------
    auto issueA = [&](int s) {   // stage s: tap = s%9, chunk = s/9
        const int tap = s % 9, ci0 = (s / 9) * 32;
        const uint32_t dst = smem_u + ((s & 1) * ASTAGE_W) * 4;
        const __half* src = g_wtap + ((size_t)tap * COUT_ + m0) * CIN_ + ci0;
#pragma unroll
        for (int i = 0; i < 2; i++) {
            int idx = tid + i * 256;             // 512 x 16B chunks
            int row = idx >> 2, cg = idx & 3;
            CP16(dst + row * 80 + cg * 16, src + (size_t)row * CIN_ + cg * 8);
        }
    };
    auto issueB = [&](int c) {   // ci-chunk c (32 ci = 16 half2 channels)
        const int c20 = c * 16;
        const uint32_t dst = smem_u + (B0_W + (c & 1) * BSTAGE_W) * 4;
#pragma unroll
        for (int i = 0; i < 6; i++) {
            int idx = tid + i * 256;             // 1536 x 16B chunks
            int c2 = idx / 96, rem = idx % 96;   // 6 rows x 16 col-chunks per c2
            int r = rem >> 4, cg = rem & 15;
            int y = y0 - 1 + r;
            if ((unsigned)y < H_)
                CP16(dst + c2 * 1760 + r * 288 + 16 + cg * 16,
                     g_xs2 + (((size_t)(b * (CIN_ / 2) + c20 + c2)) * H_ + y) * W_ + cg * 4);
        }
    };

    float acc[4][8][4];
#pragma unroll
    for (int mf = 0; mf < 4; mf++)
#pragma unroll
        for (int nf = 0; nf < 8; nf++)
#pragma unroll
            for (int k = 0; k < 4; k++) acc[mf][nf][k] = 0.f;

    // prologue
    issueB(0);
    issueA(0);
    CP_COMMIT();

    for (int s = 0; s < 144; s++) {
        CP_WAIT0();
        __syncthreads();
        if (s + 1 < 144) {
            issueA(s + 1);
            if ((s + 1) % 9 == 0) issueB((s + 1) / 9);
            CP_COMMIT();
        }

        const int tap = s % 9, chunk = s / 9;
        const int dy = tap / 3, dx = tap % 3;
        // A: row stride 20 words; frag word tig holds halves (2tig, 2tig+1)
        const uint32_t* Aw = smem + (s & 1) * ASTAGE_W + (wm * 64 + gid) * 20 + tig;
        // B: c2 stride 440 words; word = half2{ci even, ci odd} at one pixel.
        // n-warp wn owns output row y0+wn -> reads tile row (wn+dy).
        const uint32_t* Bw = smem + B0_W + (chunk & 1) * BSTAGE_W
                             + tig * 440 + (wn + dy) * 72 + gid + dx + 3;
#pragma unroll
        for (int ks = 0; ks < 2; ks++) {         // 2 x k16 per 32-ci chunk
            uint32_t b0[8], b1[8];
#pragma unroll
            for (int nf = 0; nf < 8; nf++) {
                b0[nf] = Bw[ks * 3520 + nf * 8];           // c2 = tig   (+8ks)
                b1[nf] = Bw[ks * 3520 + nf * 8 + 1760];    // c2 = tig+4 (+8ks)
            }
#pragma unroll
            for (int mf = 0; mf < 4; mf++) {
                uint32_t a0 = Aw[mf * 320 + ks * 8];        // row gid,   k lo
                uint32_t a1 = Aw[mf * 320 + ks * 8 + 160];  // row gid+8, k lo
                uint32_t a2 = Aw[mf * 320 + ks * 8 + 4];    // row gid,   k hi
                uint32_t a3 = Aw[mf * 320 + ks * 8 + 164];  // row gid+8, k hi
#pragma unroll
                for (int nf = 0; nf < 8; nf++)
                    MMA_F16(acc[mf][nf], a0, a1, a2, a3, b0[nf], b1[nf]);
            }
        }
    }

    // -------- epilogue: demodulate + store --------
    const int y = y0 + wn;
#pragma unroll
    for (int mf = 0; mf < 4; mf++) {
        const int o0 = m0 + wm * 64 + mf * 16 + gid;
        const float dmlo = g_demod[b * COUT_ + o0];
        const float dmhi = g_demod[b * COUT_ + o0 + 8];
        float* plo = out + (((size_t)b * COUT_ + o0) * H_ + y) * W_;
        float* phi = plo + 8 * (size_t)HW_;
#pragma unroll
        for (int nf = 0; nf < 8; nf++) {
            const int x = nf * 8 + 2 * tig;
            float2 vlo, vhi;
            vlo.x = acc[mf][nf][0] * dmlo;
            vlo.y = acc[mf][nf][1] * dmlo;
            vhi.x = acc[mf][nf][2] * dmhi;
            vhi.y = acc[mf][nf][3] * dmhi;
            *(float2*)(plo + x) = vlo;
            *(float2*)(phi + x) = vhi;
        }
    }
}

// ======================= host side =======================
extern "C" void kernel_launch(void* const* d_in, const int* in_sizes, int n_in,
                              void* d_out, int out_size) {
    const float* x          = (const float*)d_in[0];
    const float* style      = (const float*)d_in[1];
    const float* weight     = (const float*)d_in[2];
    const float* mod_weight = (const float*)d_in[3];
    const float* mod_bias   = (const float*)d_in[4];
    float* out = (float*)d_out;

    prep1_kernel<<<1040, 512>>>(style, mod_weight, mod_bias, weight);   // launch 1
    demod_kernel<<<B_, COUT_>>>();                                      // launch 2
    xs2_kernel<<<(B_ * (CIN_ / 2) * HW_ / 4) / 512, 512>>>(x);          // launch 3

    static bool configured = false;
    if (!configured) {
        cudaFuncSetAttribute(conv_mma_kernel,
                             cudaFuncAttributeMaxDynamicSharedMemorySize,
                             SMEM_W * 4);
        configured = true;
    }
    dim3 grid(16, 4, B_);   // (n-tiles, m-tiles, batch) = 1024 CTAs
    conv_mma_kernel<<<grid, 256, SMEM_W * 4>>>(out);                    // launch 4
}

// round 11
// speedup vs baseline: 8.9603x; 1.1334x over previous
#include <cuda_runtime.h>
#include <cuda_fp16.h>
#include <cstdint>

// ======================= problem constants =======================
#define B_    16
#define CIN_  512
#define COUT_ 512
#define H_    64
#define W_    64
#define HW_   4096
#define SDIM_ 512

static __device__ __constant__ float MOD_SCALE_C  = 0.04419417382415922f;   // 1/sqrt(512)
static __device__ __constant__ float CONV_SCALE_C = 0.014731391274719742f;  // 1/sqrt(512*9)

// ======================= device scratch (no allocs allowed) =======================
__device__ float g_s[B_ * CIN_];
__device__ float g_demod[B_ * COUT_];
__device__ float g_wsqT[CIN_ * COUT_];
// f16 scaled input, channel-pair interleaved: word[b][c2][y][x] = {x[2c2], x[2c2+1]} * s * CONV_SCALE
__device__ __align__(16) uint32_t g_xs2[B_ * (CIN_ / 2) * HW_];
// f16 weight taps: [tap][o][ci]
__device__ __align__(16) __half g_wtap[9 * COUT_ * CIN_];

// ======================= helpers =======================
__device__ __forceinline__ uint32_t smem_to_u32(const void* p) {
    uint32_t a;
    asm("{ .reg .u64 t; cvta.to.shared.u64 t, %1; cvt.u32.u64 %0, t; }" : "=r"(a) : "l"(p));
    return a;
}
__device__ __forceinline__ uint32_t pack_half2(float lo, float hi) {
    uint32_t l = (uint32_t)__half_as_ushort(__float2half_rn(lo));
    uint32_t h = (uint32_t)__half_as_ushort(__float2half_rn(hi));
    return l | (h << 16);
}

#define CP16(dst_s, src_g) \
    asm volatile("cp.async.cg.shared.global [%0], [%1], 16;" \
                 :: "r"(dst_s), "l"(src_g) : "memory")
#define CP_COMMIT() asm volatile("cp.async.commit_group;" ::: "memory")
#define CP_WAIT0()  asm volatile("cp.async.wait_group 0;" ::: "memory")

// f16 mma, fp32 accumulate: D(16x8) += A(16x16) * B(16x8)
#define MMA_F16(d, a0, a1, a2, a3, b0, b1)                                   \
    asm volatile("mma.sync.aligned.m16n8k16.row.col.f32.f16.f16.f32 "        \
        "{%0,%1,%2,%3}, {%4,%5,%6,%7}, {%8,%9}, {%0,%1,%2,%3};"              \
        : "+f"((d)[0]), "+f"((d)[1]), "+f"((d)[2]), "+f"((d)[3])             \
        : "r"(a0), "r"(a1), "r"(a2), "r"(a3), "r"(b0), "r"(b1))

// ======================= prep kernels =======================
// blocks [0,512): per-o weight processing (coalesced); [512,528): modulation.
__global__ void __launch_bounds__(512) prep_kernel(const float* __restrict__ style,
                                                   const float* __restrict__ mod_weight,
                                                   const float* __restrict__ mod_bias,
                                                   const float* __restrict__ weight) {
    const int blk = blockIdx.x, tid = threadIdx.x;
    if (blk < 512) {
        __shared__ float wrow[CIN_ * 9];
        const int o = blk;
        const float* src = weight + (size_t)o * (CIN_ * 9);
        for (int i = tid; i < CIN_ * 9; i += 512) wrow[i] = src[i];
        __syncthreads();
        const int ci = tid;
        float w[9], acc = 0.f;
#pragma unroll
        for (int t = 0; t < 9; t++) {
            w[t] = wrow[ci * 9 + t];            // stride 9 coprime 32: conflict-free
            acc = fmaf(w[t], w[t], acc);
        }
        g_wsqT[ci * COUT_ + o] = acc;
#pragma unroll
        for (int t = 0; t < 9; t++)
            g_wtap[((size_t)t * COUT_ + o) * CIN_ + ci] = __float2half_rn(w[t]);
    } else {
        __shared__ float st[SDIM_];
        const int b = blk - 512, i = tid;
        st[i] = style[b * SDIM_ + i];
        __syncthreads();
        const float* wr = mod_weight + (size_t)i * SDIM_;
        float acc = 0.f;
#pragma unroll 8
        for (int j = 0; j < SDIM_; j++) acc = fmaf(st[j], wr[j], acc);
        g_s[b * CIN_ + i] = acc * MOD_SCALE_C + mod_bias[i];
    }
}

__global__ void demod_kernel() {
    int b = blockIdx.x, o = threadIdx.x;
    __shared__ float s2[CIN_];
    float sv = g_s[b * CIN_ + o];
    s2[o] = sv * sv;
    __syncthreads();
    float acc = 0.f;
#pragma unroll 8
    for (int i = 0; i < CIN_; i++) acc = fmaf(s2[i], g_wsqT[i * COUT_ + o], acc);
    float cs2 = CONV_SCALE_C * CONV_SCALE_C;
    g_demod[b * COUT_ + o] = rsqrtf(acc * cs2 + 1e-8f);
}

// x -> f16 half2(channel-pair) images, scaled by s * CONV_SCALE
__global__ void __launch_bounds__(512) xs2_kernel(const float* __restrict__ x) {
    int idx = blockIdx.x * 512 + threadIdx.x;          // (b, c2, pix4)
    int bc2 = idx >> 10;
    int p4  = (idx & 1023) * 4;
    int b = bc2 >> 8, c2 = bc2 & 255;
    float sc0 = g_s[b * CIN_ + 2 * c2]     * CONV_SCALE_C;
    float sc1 = g_s[b * CIN_ + 2 * c2 + 1] * CONV_SCALE_C;
    const float4 v0 = *(const float4*)(x + ((size_t)(b * CIN_ + 2 * c2))     * HW_ + p4);
    const float4 v1 = *(const float4*)(x + ((size_t)(b * CIN_ + 2 * c2 + 1)) * HW_ + p4);
    uint4 r;
    r.x = pack_half2(v0.x * sc0, v1.x * sc1);
    r.y = pack_half2(v0.y * sc0, v1.y * sc1);
    r.z = pack_half2(v0.z * sc0, v1.z * sc1);
    r.w = pack_half2(v0.w * sc0, v1.w * sc1);
    ((uint4*)g_xs2)[idx] = r;
}

// ======================= main mma.sync f16 conv kernel =======================
// CTA tile: M=128 outch x N=256 px (4 rows of 64). 8 warps (2m x 4n), warp 64x64.
// 16 STAGES of 32 ci; each stage loops all 9 taps with NO internal barriers.
// A chunk: [tap(9)][row(128)][16 words], XOR chunk-swizzled (cg ^ ((row>>1)&3)).
// B chunk: 16 c2 x stride 440 (6 rows x 72 cols + 8 pad), halo shifts per tap.
//
// smem (32-bit words):
//   A: 2 x 9 x 128 x 16 = 36864 w      B: 2 x 7040 = 14080 w
#define ATAP_W   2048                    // 128 rows x 16 words
#define ACHUNK_W (9 * ATAP_W)            // 18432
#define BSTAGE_W 7040
#define B0_W     (2 * ACHUNK_W)          // 36864
#define SMEM_W   (2 * ACHUNK_W + 2 * BSTAGE_W)   // 50944 words = 203776 B

__global__ void __launch_bounds__(256, 1)
conv_mma_kernel(float* __restrict__ out) {
    extern __shared__ uint32_t smem[];
    const uint32_t smem_u = smem_to_u32(smem);

    const int tid  = threadIdx.x;
    const int wid  = tid >> 5, lane = tid & 31;
    const int gid  = lane >> 2, tig = lane & 3;
    const int wm   = wid >> 2, wn = wid & 3;      // 2 m-warps x 4 n-warps
    const int nt   = blockIdx.x, mt = blockIdx.y, b = blockIdx.z;
    const int y0   = nt * 4;
    const int m0   = mt * 128;

    // zero both B buffers once: halo cols + y-OOB rows stay zero forever.
    for (int i = tid; i < (2 * BSTAGE_W) / 4; i += 256)
        ((uint4*)(smem + B0_W))[i] = make_uint4(0, 0, 0, 0);
    __syncthreads();

    // -------- cp.async issuers --------
    auto issueA = [&](int c) {   // ci-chunk c: all 9 taps
        const int ci0 = c * 32;
        const uint32_t abase = smem_u + ((c & 1) * ACHUNK_W) * 4;
#pragma unroll
        for (int i = 0; i < 18; i++) {
            int idx = tid + i * 256;             // 4608 x 16B chunks
            int tap = idx >> 9, rem = idx & 511;
            int row = rem >> 2, cg = rem & 3;
            int dstw = tap * ATAP_W + row * 16 + ((cg ^ ((row >> 1) & 3)) << 2);
            CP16(abase + dstw * 4,
                 g_wtap + ((size_t)tap * COUT_ + m0 + row) * CIN_ + ci0 + cg * 8);
        }
    };
    auto issueB = [&](int c) {   // ci-chunk c (32 ci = 16 half2 channels)
        const int c20 = c * 16;
        const uint32_t dst = smem_u + (B0_W + (c & 1) * BSTAGE_W) * 4;
#pragma unroll
        for (int i = 0; i < 6; i++) {
            int idx = tid + i * 256;             // 1536 x 16B chunks
            int c2 = idx / 96, rem = idx % 96;
            int r = rem >> 4, cg = rem & 15;
            int y = y0 - 1 + r;
            if ((unsigned)y < H_)
                CP16(dst + c2 * 1760 + r * 288 + 16 + cg * 16,
                     g_xs2 + (((size_t)(b * (CIN_ / 2) + c20 + c2)) * H_ + y) * W_ + cg * 4);
        }
    };

    float acc[4][8][4];
#pragma unroll
    for (int mf = 0; mf < 4; mf++)
#pragma unroll
        for (int nf = 0; nf < 8; nf++)
#pragma unroll
            for (int k = 0; k < 4; k++) acc[mf][nf][k] = 0.f;

    // per-lane A swizzle constants: chunk' = chunk ^ ((row>>1)&3); the row-
    // dependent part reduces to s = (gid>>1)&3 (mf*16, wm*64, +8 are 0 mod 4).
    const int s_swz = (gid >> 1) & 3;
    const int awz[4] = { ((0 ^ s_swz) << 2) + tig, ((1 ^ s_swz) << 2) + tig,
                         ((2 ^ s_swz) << 2) + tig, ((3 ^ s_swz) << 2) + tig };

    // prologue
    issueB(0);
    issueA(0);
    CP_COMMIT();

    for (int c = 0; c < 16; c++) {
        CP_WAIT0();
        __syncthreads();
        if (c + 1 < 16) {
            issueA(c + 1);
            issueB(c + 1);
            CP_COMMIT();
        }

        const uint32_t* Ab = smem + (c & 1) * ACHUNK_W + wm * 1024;  // + wm*64 rows
        const uint32_t* Bb = smem + B0_W + (c & 1) * BSTAGE_W + tig * 440 + gid + 3;

        for (int tap = 0; tap < 9; tap++) {
            const int dy = tap / 3, dx = tap % 3;
            const uint32_t* Aw = Ab + tap * ATAP_W;
            const uint32_t* Bw = Bb + (wn + dy) * 72 + dx;
#pragma unroll
            for (int ks = 0; ks < 2; ks++) {
                uint32_t b0[8], b1[8];
#pragma unroll
                for (int nf = 0; nf < 8; nf++) {
                    b0[nf] = Bw[ks * 3520 + nf * 8];           // c2 = tig   (+8ks)
                    b1[nf] = Bw[ks * 3520 + nf * 8 + 1760];    // c2 = tig+4 (+8ks)
                }
                const int wlo = awz[2 * ks], whi = awz[2 * ks + 1];
#pragma unroll
                for (int mf = 0; mf < 4; mf++) {
                    const uint32_t* Ar = Aw + (mf * 16 + gid) * 16;
                    uint32_t a0 = Ar[wlo];          // row gid,   k lo chunk
                    uint32_t a1 = Ar[128 + wlo];    // row gid+8, k lo
                    uint32_t a2 = Ar[whi];          // row gid,   k hi
                    uint32_t a3 = Ar[128 + whi];    // row gid+8, k hi
#pragma unroll
                    for (int nf = 0; nf < 8; nf++)
                        MMA_F16(acc[mf][nf], a0, a1, a2, a3, b0[nf], b1[nf]);
                }
            }
        }
    }

    // -------- epilogue: demodulate + store --------
    const int y = y0 + wn;
#pragma unroll
    for (int mf = 0; mf < 4; mf++) {
        const int o0 = m0 + wm * 64 + mf * 16 + gid;
        const float dmlo = g_demod[b * COUT_ + o0];
        const float dmhi = g_demod[b * COUT_ + o0 + 8];
        float* plo = out + (((size_t)b * COUT_ + o0) * H_ + y) * W_;
        float* phi = plo + 8 * (size_t)HW_;
#pragma unroll
        for (int nf = 0; nf < 8; nf++) {
            const int x = nf * 8 + 2 * tig;
            float2 vlo, vhi;
            vlo.x = acc[mf][nf][0] * dmlo;
            vlo.y = acc[mf][nf][1] * dmlo;
            vhi.x = acc[mf][nf][2] * dmhi;
            vhi.y = acc[mf][nf][3] * dmhi;
            *(float2*)(plo + x) = vlo;
            *(float2*)(phi + x) = vhi;
        }
    }
}

// ======================= host side =======================
extern "C" void kernel_launch(void* const* d_in, const int* in_sizes, int n_in,
                              void* d_out, int out_size) {
    const float* x          = (const float*)d_in[0];
    const float* style      = (const float*)d_in[1];
    const float* weight     = (const float*)d_in[2];
    const float* mod_weight = (const float*)d_in[3];
    const float* mod_bias   = (const float*)d_in[4];
    float* out = (float*)d_out;

    prep_kernel<<<528, 512>>>(style, mod_weight, mod_bias, weight);
    demod_kernel<<<B_, COUT_>>>();
    xs2_kernel<<<(B_ * (CIN_ / 2) * HW_ / 4) / 512, 512>>>(x);

    static bool configured = false;
    if (!configured) {
        cudaFuncSetAttribute(conv_mma_kernel,
                             cudaFuncAttributeMaxDynamicSharedMemorySize,
                             SMEM_W * 4);
        configured = true;
    }
    dim3 grid(16, 4, B_);   // (n-tiles, m-tiles, batch) = 1024 CTAs
    conv_mma_kernel<<<grid, 256, SMEM_W * 4>>>(out);
}

// round 12
// speedup vs baseline: 9.1575x; 1.0220x over previous
#include <cuda_runtime.h>
#include <cuda_fp16.h>
#include <cstdint>

// ======================= problem constants =======================
#define B_    16
#define CIN_  512
#define COUT_ 512
#define H_    64
#define W_    64
#define HW_   4096
#define SDIM_ 512

static __device__ __constant__ float MOD_SCALE_C  = 0.04419417382415922f;   // 1/sqrt(512)
static __device__ __constant__ float CONV_SCALE_C = 0.014731391274719742f;  // 1/sqrt(512*9)

// ======================= device scratch (no allocs allowed) =======================
__device__ float g_s[B_ * CIN_];
__device__ float g_demod[B_ * COUT_];
__device__ float g_wsqT[CIN_ * COUT_];
// f16 scaled input, channel-pair interleaved: word[b][c2][y][x] = {x[2c2], x[2c2+1]} * s * CONV_SCALE
__device__ __align__(16) uint32_t g_xs2[B_ * (CIN_ / 2) * HW_];
// f16 weight taps: [tap][o][ci]
__device__ __align__(16) __half g_wtap[9 * COUT_ * CIN_];

// ======================= helpers =======================
__device__ __forceinline__ uint32_t smem_to_u32(const void* p) {
    uint32_t a;
    asm("{ .reg .u64 t; cvta.to.shared.u64 t, %1; cvt.u32.u64 %0, t; }" : "=r"(a) : "l"(p));
    return a;
}
__device__ __forceinline__ uint32_t pack_half2(float lo, float hi) {
    uint32_t l = (uint32_t)__half_as_ushort(__float2half_rn(lo));
    uint32_t h = (uint32_t)__half_as_ushort(__float2half_rn(hi));
    return l | (h << 16);
}

#define CP16(dst_s, src_g) \
    asm volatile("cp.async.cg.shared.global [%0], [%1], 16;" \
                 :: "r"(dst_s), "l"(src_g) : "memory")
#define CP_COMMIT() asm volatile("cp.async.commit_group;" ::: "memory")
#define CP_WAIT0()  asm volatile("cp.async.wait_group 0;" ::: "memory")

// f16 mma, fp32 accumulate: D(16x8) += A(16x16) * B(16x8)
#define MMA_F16(d, a0, a1, a2, a3, b0, b1)                                   \
    asm volatile("mma.sync.aligned.m16n8k16.row.col.f32.f16.f16.f32 "        \
        "{%0,%1,%2,%3}, {%4,%5,%6,%7}, {%8,%9}, {%0,%1,%2,%3};"              \
        : "+f"((d)[0]), "+f"((d)[1]), "+f"((d)[2]), "+f"((d)[3])             \
        : "r"(a0), "r"(a1), "r"(a2), "r"(a3), "r"(b0), "r"(b1))

// ldmatrix x4: loads 4 8x8 f16 matrices; lane groups 0-7/8-15/16-23/24-31 supply
// the 8 row addresses of matrices 0..3 respectively.
#define LDSM_X4(d0, d1, d2, d3, addr)                                        \
    asm volatile("ldmatrix.sync.aligned.m8n8.x4.shared.b16 {%0,%1,%2,%3}, [%4];" \
        : "=r"(d0), "=r"(d1), "=r"(d2), "=r"(d3) : "r"(addr))

// ======================= prep kernels =======================
// blocks [0,512): per-o weight processing (coalesced); [512,528): modulation.
__global__ void __launch_bounds__(512) prep_kernel(const float* __restrict__ style,
                                                   const float* __restrict__ mod_weight,
                                                   const float* __restrict__ mod_bias,
                                                   const float* __restrict__ weight) {
    const int blk = blockIdx.x, tid = threadIdx.x;
    if (blk < 512) {
        __shared__ float wrow[CIN_ * 9];
        const int o = blk;
        const float* src = weight + (size_t)o * (CIN_ * 9);
        for (int i = tid; i < CIN_ * 9; i += 512) wrow[i] = src[i];
        __syncthreads();
        const int ci = tid;
        float w[9], acc = 0.f;
#pragma unroll
        for (int t = 0; t < 9; t++) {
            w[t] = wrow[ci * 9 + t];            // stride 9 coprime 32: conflict-free
            acc = fmaf(w[t], w[t], acc);
        }
        g_wsqT[ci * COUT_ + o] = acc;
#pragma unroll
        for (int t = 0; t < 9; t++)
            g_wtap[((size_t)t * COUT_ + o) * CIN_ + ci] = __float2half_rn(w[t]);
    } else {
        __shared__ float st[SDIM_];
        const int b = blk - 512, i = tid;
        st[i] = style[b * SDIM_ + i];
        __syncthreads();
        const float* wr = mod_weight + (size_t)i * SDIM_;
        float acc = 0.f;
#pragma unroll 8
        for (int j = 0; j < SDIM_; j++) acc = fmaf(st[j], wr[j], acc);
        g_s[b * CIN_ + i] = acc * MOD_SCALE_C + mod_bias[i];
    }
}

// fused: blocks [0,8192) = x -> f16 half2 channel-pair images; [8192,8208) = demod
__global__ void __launch_bounds__(512) xs2_demod_kernel(const float* __restrict__ x) {
    if (blockIdx.x < 8192) {
        int idx = blockIdx.x * 512 + threadIdx.x;          // (b, c2, pix4)
        int bc2 = idx >> 10;
        int p4  = (idx & 1023) * 4;
        int b = bc2 >> 8, c2 = bc2 & 255;
        float sc0 = g_s[b * CIN_ + 2 * c2]     * CONV_SCALE_C;
        float sc1 = g_s[b * CIN_ + 2 * c2 + 1] * CONV_SCALE_C;
        const float4 v0 = *(const float4*)(x + ((size_t)(b * CIN_ + 2 * c2))     * HW_ + p4);
        const float4 v1 = *(const float4*)(x + ((size_t)(b * CIN_ + 2 * c2 + 1)) * HW_ + p4);
        uint4 r;
        r.x = pack_half2(v0.x * sc0, v1.x * sc1);
        r.y = pack_half2(v0.y * sc0, v1.y * sc1);
        r.z = pack_half2(v0.z * sc0, v1.z * sc1);
        r.w = pack_half2(v0.w * sc0, v1.w * sc1);
        ((uint4*)g_xs2)[idx] = r;
    } else {
        __shared__ float s2[CIN_];
        int b = blockIdx.x - 8192, o = threadIdx.x;
        float sv = g_s[b * CIN_ + o];
        s2[o] = sv * sv;
        __syncthreads();
        float acc = 0.f;
#pragma unroll 8
        for (int i = 0; i < CIN_; i++) acc = fmaf(s2[i], g_wsqT[i * COUT_ + o], acc);
        float cs2 = CONV_SCALE_C * CONV_SCALE_C;
        g_demod[b * COUT_ + o] = rsqrtf(acc * cs2 + 1e-8f);
    }
}

// ======================= main mma.sync f16 conv kernel =======================
// CTA tile: M=128 outch x N=256 px (4 rows of 64). 8 warps (2m x 4n), warp 64x64.
// 16 STAGES of 32 ci; each stage loops 9 taps x 2 k16-steps = 18 fragment steps,
// register double-buffered (prefetch step s+1 during step s mma), no barriers
// inside a stage. A via ldmatrix.x4 (XOR chunk-swizzled), B via LDS.32.
//
// smem (32-bit words):
//   A: 2 x 9 x 128 x 16 = 36864 w      B: 2 x 7040 = 14080 w
#define ATAP_W   2048                    // 128 rows x 16 words
#define ACHUNK_W (9 * ATAP_W)            // 18432
#define BSTAGE_W 7040
#define B0_W     (2 * ACHUNK_W)          // 36864
#define SMEM_W   (2 * ACHUNK_W + 2 * BSTAGE_W)   // 50944 words = 203776 B

__global__ void __launch_bounds__(256, 1)
conv_mma_kernel(float* __restrict__ out) {
    extern __shared__ uint32_t smem[];
    const uint32_t smem_u = smem_to_u32(smem);

    const int tid  = threadIdx.x;
    const int wid  = tid >> 5, lane = tid & 31;
    const int gid  = lane >> 2, tig = lane & 3;
    const int wm   = wid >> 2, wn = wid & 3;      // 2 m-warps x 4 n-warps
    const int nt   = blockIdx.x, mt = blockIdx.y, b = blockIdx.z;
    const int y0   = nt * 4;
    const int m0   = mt * 128;

    // zero both B buffers once: halo cols + y-OOB rows stay zero forever.
    for (int i = tid; i < (2 * BSTAGE_W) / 4; i += 256)
        ((uint4*)(smem + B0_W))[i] = make_uint4(0, 0, 0, 0);
    __syncthreads();

    // -------- cp.async issuers --------
    auto issueA = [&](int c) {   // ci-chunk c: all 9 taps
        const int ci0 = c * 32;
        const uint32_t abase = smem_u + ((c & 1) * ACHUNK_W) * 4;
#pragma unroll
        for (int i = 0; i < 18; i++) {
            int idx = tid + i * 256;             // 4608 x 16B chunks
            int tap = idx >> 9, rem = idx & 511;
            int row = rem >> 2, cg = rem & 3;
            int dstw = tap * ATAP_W + row * 16 + ((cg ^ ((row >> 1) & 3)) << 2);
            CP16(abase + dstw * 4,
                 g_wtap + ((size_t)tap * COUT_ + m0 + row) * CIN_ + ci0 + cg * 8);
        }
    };
    auto issueB = [&](int c) {   // ci-chunk c (32 ci = 16 half2 channels)
        const int c20 = c * 16;
        const uint32_t dst = smem_u + (B0_W + (c & 1) * BSTAGE_W) * 4;
#pragma unroll
        for (int i = 0; i < 6; i++) {
            int idx = tid + i * 256;             // 1536 x 16B chunks
            int c2 = idx / 96, rem = idx % 96;
            int r = rem >> 4, cg = rem & 15;
            int y = y0 - 1 + r;
            if ((unsigned)y < H_)
                CP16(dst + c2 * 1760 + r * 288 + 16 + cg * 16,
                     g_xs2 + (((size_t)(b * (CIN_ / 2) + c20 + c2)) * H_ + y) * W_ + cg * 4);
        }
    };

    float acc[4][8][4];
#pragma unroll
    for (int mf = 0; mf < 4; mf++)
#pragma unroll
        for (int nf = 0; nf < 8; nf++)
#pragma unroll
            for (int k = 0; k < 4; k++) acc[mf][nf][k] = 0.f;

    // -------- per-lane ldmatrix addressing (matrix j = lane>>3, row r = lane&7) --
    // A word offset = tap*ATAP_W + row*16 + ((cg ^ ((row>>1)&3))<<2), where for
    // matrix j of (mf,ks): row = wm*64 + mf*16 + 8*(j&1) + r, cg = 2ks + (j>>1).
    // (row>>1)&3 reduces to (r>>1)&3 since wm*64, mf*16, 8*(j&1) are 0 mod 8.
    const int jj = lane >> 3, rr = lane & 7;
    const int sl = (rr >> 1) & 3;
    const uint32_t a_row_w  = (uint32_t)((wm * 64 + 8 * (jj & 1) + rr) * 16);
    const uint32_t a_cg_w0  = (uint32_t)((((jj >> 1) + 0) ^ sl) << 2);
    const uint32_t a_cg_w1  = (uint32_t)((((jj >> 1) + 2) ^ sl) << 2);

    // fragment double buffers
    uint32_t fa[2][4][4];
    uint32_t fb0[2][8], fb1[2][8];

    const uint32_t* Bbase = smem + B0_W + tig * 440 + gid + 3;

    auto load_step = [&](int c, int step, int p) {
        const int tap = step >> 1, ks = step & 1;
        const int dy = tap / 3, dx = tap % 3;
        const uint32_t abase = smem_u
            + (((c & 1) * ACHUNK_W + tap * ATAP_W + a_row_w
                + (ks ? a_cg_w1 : a_cg_w0)) << 2);
#pragma unroll
        for (int mf = 0; mf < 4; mf++)
            LDSM_X4(fa[p][mf][0], fa[p][mf][1], fa[p][mf][2], fa[p][mf][3],
                    abase + (uint32_t)(mf * 256 * 4));
        const uint32_t* Bw = Bbase + (c & 1) * BSTAGE_W + (wn + dy) * 72 + dx
                             + ks * 3520;
#pragma unroll
        for (int nf = 0; nf < 8; nf++) {
            fb0[p][nf] = Bw[nf * 8];            // c2 = tig
            fb1[p][nf] = Bw[nf * 8 + 1760];     // c2 = tig+4
        }
    };

    // prologue
    issueB(0);
    issueA(0);
    CP_COMMIT();

    for (int c = 0; c < 16; c++) {
        CP_WAIT0();
        __syncthreads();
        if (c + 1 < 16) {
            issueA(c + 1);
            issueB(c + 1);
            CP_COMMIT();
        }

        load_step(c, 0, 0);
#pragma unroll
        for (int step = 0; step < 18; step++) {
            const int p = step & 1;
            if (step + 1 < 18) load_step(c, step + 1, p ^ 1);
#pragma unroll
            for (int mf = 0; mf < 4; mf++)
#pragma unroll
                for (int nf = 0; nf < 8; nf++)
                    MMA_F16(acc[mf][nf], fa[p][mf][0], fa[p][mf][1],
                            fa[p][mf][2], fa[p][mf][3], fb0[p][nf], fb1[p][nf]);
        }
    }

    // -------- epilogue: demodulate + store --------
    const int y = y0 + wn;
#pragma unroll
    for (int mf = 0; mf < 4; mf++) {
        const int o0 = m0 + wm * 64 + mf * 16 + gid;
        const float dmlo = g_demod[b * COUT_ + o0];
        const float dmhi = g_demod[b * COUT_ + o0 + 8];
        float* plo = out + (((size_t)b * COUT_ + o0) * H_ + y) * W_;
        float* phi = plo + 8 * (size_t)HW_;
#pragma unroll
        for (int nf = 0; nf < 8; nf++) {
            const int x = nf * 8 + 2 * tig;
            float2 vlo, vhi;
            vlo.x = acc[mf][nf][0] * dmlo;
            vlo.y = acc[mf][nf][1] * dmlo;
            vhi.x = acc[mf][nf][2] * dmhi;
            vhi.y = acc[mf][nf][3] * dmhi;
            *(float2*)(plo + x) = vlo;
            *(float2*)(phi + x) = vhi;
        }
    }
}

// ======================= host side =======================
extern "C" void kernel_launch(void* const* d_in, const int* in_sizes, int n_in,
                              void* d_out, int out_size) {
    const float* x          = (const float*)d_in[0];
    const float* style      = (const float*)d_in[1];
    const float* weight     = (const float*)d_in[2];
    const float* mod_weight = (const float*)d_in[3];
    const float* mod_bias   = (const float*)d_in[4];
    float* out = (float*)d_out;

    prep_kernel<<<528, 512>>>(style, mod_weight, mod_bias, weight);
    xs2_demod_kernel<<<8208, 512>>>(x);

    static bool configured = false;
    if (!configured) {
        cudaFuncSetAttribute(conv_mma_kernel,
                             cudaFuncAttributeMaxDynamicSharedMemorySize,
                             SMEM_W * 4);
        configured = true;
    }
    dim3 grid(16, 4, B_);   // (n-tiles, m-tiles, batch) = 1024 CTAs
    conv_mma_kernel<<<grid, 256, SMEM_W * 4>>>(out);
}

// round 14
// speedup vs baseline: 9.2179x; 1.0066x over previous
#include <cuda_runtime.h>
#include <cuda_fp16.h>
#include <cstdint>

// ======================= problem constants =======================
#define B_    16
#define CIN_  512
#define COUT_ 512
#define H_    64
#define W_    64
#define HW_   4096
#define SDIM_ 512

static __device__ __constant__ float MOD_SCALE_C  = 0.04419417382415922f;   // 1/sqrt(512)
static __device__ __constant__ float CONV_SCALE_C = 0.014731391274719742f;  // 1/sqrt(512*9)

// ======================= device scratch (no allocs allowed) =======================
__device__ float g_s[B_ * CIN_];
__device__ float g_demod[B_ * COUT_];
__device__ float g_wsqT[CIN_ * COUT_];
// f16 scaled input, channel-pair interleaved: word[b][c2][y][x] = {x[2c2], x[2c2+1]} * s * CONV_SCALE
__device__ __align__(16) uint32_t g_xs2[B_ * (CIN_ / 2) * HW_];
// f16 weight taps: [tap][o][ci]
__device__ __align__(16) __half g_wtap[9 * COUT_ * CIN_];

// ======================= helpers =======================
__device__ __forceinline__ uint32_t smem_to_u32(const void* p) {
    uint32_t a;
    asm("{ .reg .u64 t; cvta.to.shared.u64 t, %1; cvt.u32.u64 %0, t; }" : "=r"(a) : "l"(p));
    return a;
}
__device__ __forceinline__ uint32_t pack_half2(float lo, float hi) {
    uint32_t l = (uint32_t)__half_as_ushort(__float2half_rn(lo));
    uint32_t h = (uint32_t)__half_as_ushort(__float2half_rn(hi));
    return l | (h << 16);
}

#define CP16(dst_s, src_g) \
    asm volatile("cp.async.cg.shared.global [%0], [%1], 16;" \
                 :: "r"(dst_s), "l"(src_g) : "memory")
#define CP_COMMIT() asm volatile("cp.async.commit_group;" ::: "memory")
#define CP_WAIT0()  asm volatile("cp.async.wait_group 0;" ::: "memory")

// f16 mma, fp32 accumulate: D(16x8) += A(16x16) * B(16x8)
#define MMA_F16(d, a0, a1, a2, a3, b0, b1)                                   \
    asm volatile("mma.sync.aligned.m16n8k16.row.col.f32.f16.f16.f32 "        \
        "{%0,%1,%2,%3}, {%4,%5,%6,%7}, {%8,%9}, {%0,%1,%2,%3};"              \
        : "+f"((d)[0]), "+f"((d)[1]), "+f"((d)[2]), "+f"((d)[3])             \
        : "r"(a0), "r"(a1), "r"(a2), "r"(a3), "r"(b0), "r"(b1))

// ldmatrix x4: loads 4 8x8 f16 matrices; lane groups 0-7/8-15/16-23/24-31 supply
// the 8 row addresses of matrices 0..3 respectively.
#define LDSM_X4(d0, d1, d2, d3, addr)                                        \
    asm volatile("ldmatrix.sync.aligned.m8n8.x4.shared.b16 {%0,%1,%2,%3}, [%4];" \
        : "=r"(d0), "=r"(d1), "=r"(d2), "=r"(d3) : "r"(addr))

// ======================= prep kernel (flat, latency-friendly) =======================
// blocks [0,16): modulation; [16,528): wsq; [528,1040): wtap.  512 threads each.
// wsq/wtap: one thread per (o,ci) or (i,o) pair, 9 strided loads — measured 6.8us
// for wtap in earlier rounds (vs 144us for the smem-staged variant).
__global__ void __launch_bounds__(512) prep_kernel(const float* __restrict__ style,
                                                   const float* __restrict__ mod_weight,
                                                   const float* __restrict__ mod_bias,
                                                   const float* __restrict__ weight) {
    const int blk = blockIdx.x, tid = threadIdx.x;
    if (blk < 16) {
        __shared__ float st[SDIM_];
        const int b = blk, i = tid;
        st[i] = style[b * SDIM_ + i];
        __syncthreads();
        const float* wr = mod_weight + (size_t)i * SDIM_;
        float acc = 0.f;
#pragma unroll 8
        for (int j = 0; j < SDIM_; j++) acc = fmaf(st[j], wr[j], acc);
        g_s[b * CIN_ + i] = acc * MOD_SCALE_C + mod_bias[i];
    } else if (blk < 528) {
        int idx = (blk - 16) * 512 + tid;       // i*COUT + o
        int i = idx / COUT_, o = idx % COUT_;
        const float* w = weight + ((size_t)o * CIN_ + i) * 9;
        float acc = 0.f;
#pragma unroll
        for (int t = 0; t < 9; t++) acc = fmaf(w[t], w[t], acc);
        g_wsqT[i * COUT_ + o] = acc;
    } else {
        int idx = (blk - 528) * 512 + tid;      // o*512 + ci
        int o = idx / CIN_, ci = idx % CIN_;
        const float* w = weight + (size_t)idx * 9;
#pragma unroll
        for (int t = 0; t < 9; t++)
            g_wtap[((size_t)t * COUT_ + o) * CIN_ + ci] = __float2half_rn(w[t]);
    }
}

// fused: blocks [0,8192) = x -> f16 half2 channel-pair images; [8192,8208) = demod
__global__ void __launch_bounds__(512) xs2_demod_kernel(const float* __restrict__ x) {
    if (blockIdx.x < 8192) {
        int idx = blockIdx.x * 512 + threadIdx.x;          // (b, c2, pix4)
        int bc2 = idx >> 10;
        int p4  = (idx & 1023) * 4;
        int b = bc2 >> 8, c2 = bc2 & 255;
        float sc0 = g_s[b * CIN_ + 2 * c2]     * CONV_SCALE_C;
        float sc1 = g_s[b * CIN_ + 2 * c2 + 1] * CONV_SCALE_C;
        const float4 v0 = *(const float4*)(x + ((size_t)(b * CIN_ + 2 * c2))     * HW_ + p4);
        const float4 v1 = *(const float4*)(x + ((size_t)(b * CIN_ + 2 * c2 + 1)) * HW_ + p4);
        uint4 r;
        r.x = pack_half2(v0.x * sc0, v1.x * sc1);
        r.y = pack_half2(v0.y * sc0, v1.y * sc1);
        r.z = pack_half2(v0.z * sc0, v1.z * sc1);
        r.w = pack_half2(v0.w * sc0, v1.w * sc1);
        ((uint4*)g_xs2)[idx] = r;
    } else {
        __shared__ float s2[CIN_];
        int b = blockIdx.x - 8192, o = threadIdx.x;
        float sv = g_s[b * CIN_ + o];
        s2[o] = sv * sv;
        __syncthreads();
        float acc = 0.f;
#pragma unroll 8
        for (int i = 0; i < CIN_; i++) acc = fmaf(s2[i], g_wsqT[i * COUT_ + o], acc);
        float cs2 = CONV_SCALE_C * CONV_SCALE_C;
        g_demod[b * COUT_ + o] = rsqrtf(acc * cs2 + 1e-8f);
    }
}

// ======================= main mma.sync f16 conv kernel =======================
// CTA tile: M=128 outch x N=256 px (4 rows of 64). 8 warps (2m x 4n), warp 64x64.
// 16 STAGES of 32 ci; each stage loops 9 taps x 2 k16-steps = 18 fragment steps,
// register double-buffered (prefetch step s+1 during step s mma), no barriers
// inside a stage. A via ldmatrix.x4 (XOR chunk-swizzled), B via LDS.32.
//
// smem (32-bit words):
//   A: 2 x 9 x 128 x 16 = 36864 w      B: 2 x 7040 = 14080 w
#define ATAP_W   2048                    // 128 rows x 16 words
#define ACHUNK_W (9 * ATAP_W)            // 18432
#define BSTAGE_W 7040
#define B0_W     (2 * ACHUNK_W)          // 36864
#define SMEM_W   (2 * ACHUNK_W + 2 * BSTAGE_W)   // 50944 words = 203776 B

__global__ void __launch_bounds__(256, 1)
conv_mma_kernel(float* __restrict__ out) {
    extern __shared__ uint32_t smem[];
    const uint32_t smem_u = smem_to_u32(smem);

    const int tid  = threadIdx.x;
    const int wid  = tid >> 5, lane = tid & 31;
    const int gid  = lane >> 2, tig = lane & 3;
    const int wm   = wid >> 2, wn = wid & 3;      // 2 m-warps x 4 n-warps
    const int nt   = blockIdx.x, mt = blockIdx.y, b = blockIdx.z;
    const int y0   = nt * 4;
    const int m0   = mt * 128;

    // zero both B buffers once: halo cols + y-OOB rows stay zero forever.
    for (int i = tid; i < (2 * BSTAGE_W) / 4; i += 256)
        ((uint4*)(smem + B0_W))[i] = make_uint4(0, 0, 0, 0);
    __syncthreads();

    // -------- cp.async issuers --------
    auto issueA = [&](int c) {   // ci-chunk c: all 9 taps
        const int ci0 = c * 32;
        const uint32_t abase = smem_u + ((c & 1) * ACHUNK_W) * 4;
#pragma unroll
        for (int i = 0; i < 18; i++) {
            int idx = tid + i * 256;             // 4608 x 16B chunks
            int tap = idx >> 9, rem = idx & 511;
            int row = rem >> 2, cg = rem & 3;
            int dstw = tap * ATAP_W + row * 16 + ((cg ^ ((row >> 1) & 3)) << 2);
            CP16(abase + dstw * 4,
                 g_wtap + ((size_t)tap * COUT_ + m0 + row) * CIN_ + ci0 + cg * 8);
        }
    };
    auto issueB = [&](int c) {   // ci-chunk c (32 ci = 16 half2 channels)
        const int c20 = c * 16;
        const uint32_t dst = smem_u + (B0_W + (c & 1) * BSTAGE_W) * 4;
#pragma unroll
        for (int i = 0; i < 6; i++) {
            int idx = tid + i * 256;             // 1536 x 16B chunks
            int c2 = idx / 96, rem = idx % 96;
            int r = rem >> 4, cg = rem & 15;
            int y = y0 - 1 + r;
            if ((unsigned)y < H_)
                CP16(dst + c2 * 1760 + r * 288 + 16 + cg * 16,
                     g_xs2 + (((size_t)(b * (CIN_ / 2) + c20 + c2)) * H_ + y) * W_ + cg * 4);
        }
    };

    float acc[4][8][4];
#pragma unroll
    for (int mf = 0; mf < 4; mf++)
#pragma unroll
        for (int nf = 0; nf < 8; nf++)
#pragma unroll
            for (int k = 0; k < 4; k++) acc[mf][nf][k] = 0.f;

    // -------- per-lane ldmatrix addressing (matrix j = lane>>3, row r = lane&7) --
    const int jj = lane >> 3, rr = lane & 7;
    const int sl = (rr >> 1) & 3;
    const uint32_t a_row_w  = (uint32_t)((wm * 64 + 8 * (jj & 1) + rr) * 16);
    const uint32_t a_cg_w0  = (uint32_t)((((jj >> 1) + 0) ^ sl) << 2);
    const uint32_t a_cg_w1  = (uint32_t)((((jj >> 1) + 2) ^ sl) << 2);

    // fragment double buffers
    uint32_t fa[2][4][4];
    uint32_t fb0[2][8], fb1[2][8];

    const uint32_t* Bbase = smem + B0_W + tig * 440 + gid + 3;

    auto load_step = [&](int c, int step, int p) {
        const int tap = step >> 1, ks = step & 1;
        const int dy = tap / 3, dx = tap % 3;
        const uint32_t abase = smem_u
            + (((c & 1) * ACHUNK_W + tap * ATAP_W + a_row_w
                + (ks ? a_cg_w1 : a_cg_w0)) << 2);
#pragma unroll
        for (int mf = 0; mf < 4; mf++)
            LDSM_X4(fa[p][mf][0], fa[p][mf][1], fa[p][mf][2], fa[p][mf][3],
                    abase + (uint32_t)(mf * 256 * 4));
        const uint32_t* Bw = Bbase + (c & 1) * BSTAGE_W + (wn + dy) * 72 + dx
                             + ks * 3520;
#pragma unroll
        for (int nf = 0; nf < 8; nf++) {
            fb0[p][nf] = Bw[nf * 8];            // c2 = tig
            fb1[p][nf] = Bw[nf * 8 + 1760];     // c2 = tig+4
        }
    };

    // prologue
    issueB(0);
    issueA(0);
    CP_COMMIT();

    for (int c = 0; c < 16; c++) {
        CP_WAIT0();
        __syncthreads();
        if (c + 1 < 16) {
            issueA(c + 1);
            issueB(c + 1);
            CP_COMMIT();
        }

        load_step(c, 0, 0);
#pragma unroll
        for (int step = 0; step < 18; step++) {
            const int p = step & 1;
            if (step + 1 < 18) load_step(c, step + 1, p ^ 1);
#pragma unroll
            for (int mf = 0; mf < 4; mf++)
#pragma unroll
                for (int nf = 0; nf < 8; nf++)
                    MMA_F16(acc[mf][nf], fa[p][mf][0], fa[p][mf][1],
                            fa[p][mf][2], fa[p][mf][3], fb0[p][nf], fb1[p][nf]);
        }
    }

    // -------- epilogue: demodulate + store --------
    const int y = y0 + wn;
#pragma unroll
    for (int mf = 0; mf < 4; mf++) {
        const int o0 = m0 + wm * 64 + mf * 16 + gid;
        const float dmlo = g_demod[b * COUT_ + o0];
        const float dmhi = g_demod[b * COUT_ + o0 + 8];
        float* plo = out + (((size_t)b * COUT_ + o0) * H_ + y) * W_;
        float* phi = plo + 8 * (size_t)HW_;
#pragma unroll
        for (int nf = 0; nf < 8; nf++) {
            const int x = nf * 8 + 2 * tig;
            float2 vlo, vhi;
            vlo.x = acc[mf][nf][0] * dmlo;
            vlo.y = acc[mf][nf][1] * dmlo;
            vhi.x = acc[mf][nf][2] * dmhi;
            vhi.y = acc[mf][nf][3] * dmhi;
            *(float2*)(plo + x) = vlo;
            *(float2*)(phi + x) = vhi;
        }
    }
}

// ======================= host side =======================
extern "C" void kernel_launch(void* const* d_in, const int* in_sizes, int n_in,
                              void* d_out, int out_size) {
    const float* x          = (const float*)d_in[0];
    const float* style      = (const float*)d_in[1];
    const float* weight     = (const float*)d_in[2];
    const float* mod_weight = (const float*)d_in[3];
    const float* mod_bias   = (const float*)d_in[4];
    float* out = (float*)d_out;

    prep_kernel<<<1040, 512>>>(style, mod_weight, mod_bias, weight);
    xs2_demod_kernel<<<8208, 512>>>(x);

    static bool configured = false;
    if (!configured) {
        cudaFuncSetAttribute(conv_mma_kernel,
                             cudaFuncAttributeMaxDynamicSharedMemorySize,
                             SMEM_W * 4);
        configured = true;
    }
    dim3 grid(16, 4, B_);   // (n-tiles, m-tiles, batch) = 1024 CTAs
    conv_mma_kernel<<<grid, 256, SMEM_W * 4>>>(out);
}